// round 4
// baseline (speedup 1.0000x reference)
#include <cuda_runtime.h>
#include <cstdint>

#define N_NODES 100000
#define N_EDGES 3200000
#define IN_FEAT 256
#define OUT_FEAT 128

// Scratch (no dynamic alloc allowed)
__device__ int g_row_ptr[N_NODES + 1];
__device__ uint32_t g_wt[IN_FEAT * OUT_FEAT];   // W pre-converted to tf32 (rna), [k][n]

__device__ __forceinline__ uint32_t smem_u32(const void* p) {
    uint32_t a;
    asm("{ .reg .u64 t; cvta.to.shared.u64 t, %1; cvt.u32.u64 %0, t; }" : "=r"(a) : "l"(p));
    return a;
}
__device__ __forceinline__ uint32_t f2tf32(float f) {
    uint32_t r;
    asm("cvt.rna.tf32.f32 %0, %1;" : "=r"(r) : "f"(f));
    return r;
}
__device__ __forceinline__ void cp16(uint32_t dst, const void* src) {
    asm volatile("cp.async.cg.shared.global [%0], [%1], 16;" :: "r"(dst), "l"(src));
}
#define CP_COMMIT() asm volatile("cp.async.commit_group;" ::: "memory")
#define CP_WAIT0()  asm volatile("cp.async.wait_group 0;" ::: "memory")

// ---------------------------------------------------------------------------
// wt_kernel: elementwise rna-convert W -> g_wt (same [256][128] layout)
// ---------------------------------------------------------------------------
__global__ void wt_kernel(const float* __restrict__ W) {
    int t = blockIdx.x * blockDim.x + threadIdx.x;
    if (t < IN_FEAT * OUT_FEAT) g_wt[t] = f2tf32(__ldg(W + t));
}

// ---------------------------------------------------------------------------
// rowptr via linear boundary scan (edge_row sorted ascending)
// ---------------------------------------------------------------------------
__global__ void rowptr_scan(const int* __restrict__ edge_row) {
    int e = blockIdx.x * blockDim.x + threadIdx.x;
    if (e >= N_EDGES) return;
    int cur  = __ldg(edge_row + e);
    int prev = (e == 0) ? -1 : __ldg(edge_row + e - 1);
    for (int i = prev + 1; i <= cur; i++) g_row_ptr[i] = e;
    if (e == N_EDGES - 1)
        for (int i = cur + 1; i <= N_NODES; i++) g_row_ptr[i] = N_EDGES;
}

// ---------------------------------------------------------------------------
// GEMM v2: femb = feat @ W, tf32 mma.sync m16n8k8.
// CTA tile 256x128, BK=16, 8 warps (4M x 2N), warp tile 64x64.
// As: single buffer, pitch 20 (conflict-free frag LDS), register-staged + rna.
// Bs: double buffer, pitch 136 (conflict-free), filled by cp.async from g_wt.
// ---------------------------------------------------------------------------
#define BM 256
#define BK 16
#define NCH (IN_FEAT / BK)   // 16
#define AP 20
#define BP 136
#define AS_U32 (BM * AP)         // 5120
#define BS_U32 (BK * BP)         // 2176

__global__ __launch_bounds__(256) void gemm_tf32_v2(
    const float* __restrict__ A,   // [M, 256] fp32
    float* __restrict__ C)         // [M, 128] fp32
{
    __shared__ uint32_t As[AS_U32];
    __shared__ uint32_t Bs[2 * BS_U32];

    const int tid  = threadIdx.x;
    const int lane = tid & 31;
    const int wid  = tid >> 5;
    const int wm   = wid & 3;          // rows [wm*64, wm*64+64)
    const int wn   = wid >> 2;         // cols [wn*64, wn*64+64)
    const int row0 = blockIdx.x * BM;
    const int g    = lane >> 2;        // 0..7
    const int q    = lane & 3;         // 0..3

    const uint32_t sbB = smem_u32(Bs);

    float acc[4][8][4];
#pragma unroll
    for (int mi = 0; mi < 4; mi++)
#pragma unroll
        for (int ni = 0; ni < 8; ni++)
#pragma unroll
            for (int j = 0; j < 4; j++) acc[mi][ni][j] = 0.0f;

    // A staging indices: thread handles rows ar+64j (j=0..3), k cols ac..ac+3
    const int ar = tid >> 2;           // 0..63
    const int ac = (tid & 3) * 4;      // 0,4,8,12
    // B cp.async indices: thread handles 2 of 512 16B chunks
    const int bk0 = tid >> 5, bn0 = (tid & 31) * 4;          // chunk tid
    const int bk1 = (tid + 256) >> 5, bn1 = bn0;             // chunk tid+256

    float4 ra[4];

    // ---- prologue: B chunk0 via cp.async, A chunk0 via regs ----
    cp16(sbB + (bk0 * BP + bn0) * 4, g_wt + bk0 * OUT_FEAT + bn0);
    cp16(sbB + (bk1 * BP + bn1) * 4, g_wt + bk1 * OUT_FEAT + bn1);
    CP_COMMIT();
#pragma unroll
    for (int j = 0; j < 4; j++) {
        int r = row0 + ar + 64 * j;
        ra[j] = (r < N_NODES) ? *(const float4*)(A + (size_t)r * IN_FEAT + ac)
                              : make_float4(0.f, 0.f, 0.f, 0.f);
    }
#pragma unroll
    for (int j = 0; j < 4; j++) {
        uint4 v = make_uint4(f2tf32(ra[j].x), f2tf32(ra[j].y), f2tf32(ra[j].z), f2tf32(ra[j].w));
        *(uint4*)&As[(ar + 64 * j) * AP + ac] = v;
    }
    CP_WAIT0();
    __syncthreads();

    for (int c = 0; c < NCH; c++) {
        const uint32_t* bsc = Bs + (c & 1) * BS_U32;

        // issue next B copy + next A global loads (overlap with compute)
        if (c + 1 < NCH) {
            const int k0 = (c + 1) * BK;
            uint32_t bdst = sbB + ((c + 1) & 1) * BS_U32 * 4;
            cp16(bdst + (bk0 * BP + bn0) * 4, g_wt + (k0 + bk0) * OUT_FEAT + bn0);
            cp16(bdst + (bk1 * BP + bn1) * 4, g_wt + (k0 + bk1) * OUT_FEAT + bn1);
            CP_COMMIT();
#pragma unroll
            for (int j = 0; j < 4; j++) {
                int r = row0 + ar + 64 * j;
                ra[j] = (r < N_NODES) ? *(const float4*)(A + (size_t)r * IN_FEAT + k0 + ac)
                                      : make_float4(0.f, 0.f, 0.f, 0.f);
            }
        }

        // compute chunk c: two k8 steps
#pragma unroll
        for (int ks = 0; ks < BK; ks += 8) {
            uint32_t af[4][4];
#pragma unroll
            for (int mi = 0; mi < 4; mi++) {
                int m = wm * 64 + mi * 16 + g;
                af[mi][0] = As[m * AP + ks + q];
                af[mi][1] = As[(m + 8) * AP + ks + q];
                af[mi][2] = As[m * AP + ks + q + 4];
                af[mi][3] = As[(m + 8) * AP + ks + q + 4];
            }
            uint32_t bf[8][2];
#pragma unroll
            for (int ni = 0; ni < 8; ni++) {
                int n = wn * 64 + ni * 8 + g;
                bf[ni][0] = bsc[(ks + q) * BP + n];
                bf[ni][1] = bsc[(ks + q + 4) * BP + n];
            }
#pragma unroll
            for (int mi = 0; mi < 4; mi++)
#pragma unroll
                for (int ni = 0; ni < 8; ni++) {
                    asm volatile(
                        "mma.sync.aligned.m16n8k8.row.col.f32.tf32.tf32.f32 "
                        "{%0,%1,%2,%3}, {%4,%5,%6,%7}, {%8,%9}, {%0,%1,%2,%3};"
                        : "+f"(acc[mi][ni][0]), "+f"(acc[mi][ni][1]),
                          "+f"(acc[mi][ni][2]), "+f"(acc[mi][ni][3])
                        : "r"(af[mi][0]), "r"(af[mi][1]), "r"(af[mi][2]), "r"(af[mi][3]),
                          "r"(bf[ni][0]), "r"(bf[ni][1]));
                }
        }

        if (c + 1 < NCH) {
            __syncthreads();   // all warps done reading As chunk c
#pragma unroll
            for (int j = 0; j < 4; j++) {
                uint4 v = make_uint4(f2tf32(ra[j].x), f2tf32(ra[j].y),
                                     f2tf32(ra[j].z), f2tf32(ra[j].w));
                *(uint4*)&As[(ar + 64 * j) * AP + ac] = v;
            }
            CP_WAIT0();        // B chunk c+1 landed
            __syncthreads();
        }
    }

    // ---- epilogue: warp tile 64x64 ----
#pragma unroll
    for (int mi = 0; mi < 4; mi++) {
        int r1 = row0 + wm * 64 + mi * 16 + g;
        int r2 = r1 + 8;
#pragma unroll
        for (int ni = 0; ni < 8; ni++) {
            int col = wn * 64 + ni * 8 + 2 * q;
            if (r1 < N_NODES)
                *(float2*)(C + (size_t)r1 * OUT_FEAT + col) =
                    make_float2(acc[mi][ni][0], acc[mi][ni][1]);
            if (r2 < N_NODES)
                *(float2*)(C + (size_t)r2 * OUT_FEAT + col) =
                    make_float2(acc[mi][ni][2], acc[mi][ni][3]);
        }
    }
}

// ---------------------------------------------------------------------------
// SpMM: one warp per node; lane l owns columns [4l, 4l+4). No atomics.
// ---------------------------------------------------------------------------
__global__ __launch_bounds__(256) void spmm_kernel(
    const int* __restrict__ edge_col,
    const float* __restrict__ edge_val,
    const float* __restrict__ femb,
    float* __restrict__ x)
{
    int warp = (blockIdx.x * blockDim.x + threadIdx.x) >> 5;
    if (warp >= N_NODES) return;
    int lane = threadIdx.x & 31;

    int s = g_row_ptr[warp];
    int e = g_row_ptr[warp + 1];

    float4 acc = make_float4(0.f, 0.f, 0.f, 0.f);
    int i = s;
    for (; i + 4 <= e; i += 4) {
        int c0 = __ldg(edge_col + i + 0);
        int c1 = __ldg(edge_col + i + 1);
        int c2 = __ldg(edge_col + i + 2);
        int c3 = __ldg(edge_col + i + 3);
        float v0 = __ldg(edge_val + i + 0);
        float v1 = __ldg(edge_val + i + 1);
        float v2 = __ldg(edge_val + i + 2);
        float v3 = __ldg(edge_val + i + 3);
        float4 f0 = *(const float4*)(femb + (size_t)c0 * OUT_FEAT + lane * 4);
        float4 f1 = *(const float4*)(femb + (size_t)c1 * OUT_FEAT + lane * 4);
        float4 f2 = *(const float4*)(femb + (size_t)c2 * OUT_FEAT + lane * 4);
        float4 f3 = *(const float4*)(femb + (size_t)c3 * OUT_FEAT + lane * 4);
        acc.x = fmaf(v0, f0.x, acc.x); acc.y = fmaf(v0, f0.y, acc.y);
        acc.z = fmaf(v0, f0.z, acc.z); acc.w = fmaf(v0, f0.w, acc.w);
        acc.x = fmaf(v1, f1.x, acc.x); acc.y = fmaf(v1, f1.y, acc.y);
        acc.z = fmaf(v1, f1.z, acc.z); acc.w = fmaf(v1, f1.w, acc.w);
        acc.x = fmaf(v2, f2.x, acc.x); acc.y = fmaf(v2, f2.y, acc.y);
        acc.z = fmaf(v2, f2.z, acc.z); acc.w = fmaf(v2, f2.w, acc.w);
        acc.x = fmaf(v3, f3.x, acc.x); acc.y = fmaf(v3, f3.y, acc.y);
        acc.z = fmaf(v3, f3.z, acc.z); acc.w = fmaf(v3, f3.w, acc.w);
    }
    for (; i < e; i++) {
        int c = __ldg(edge_col + i);
        float v = __ldg(edge_val + i);
        float4 f = *(const float4*)(femb + (size_t)c * OUT_FEAT + lane * 4);
        acc.x = fmaf(v, f.x, acc.x); acc.y = fmaf(v, f.y, acc.y);
        acc.z = fmaf(v, f.z, acc.z); acc.w = fmaf(v, f.w, acc.w);
    }
    *(float4*)(x + (size_t)warp * OUT_FEAT + lane * 4) = acc;
}

// ---------------------------------------------------------------------------
// Launch. Inputs: feat, edge_row, edge_col, edge_val, weight.
// ---------------------------------------------------------------------------
extern "C" void kernel_launch(void* const* d_in, const int* in_sizes, int n_in,
                              void* d_out, int out_size)
{
    const float* feat     = (const float*)d_in[0];
    const int*   edge_row = (const int*)d_in[1];
    const int*   edge_col = (const int*)d_in[2];
    const float* edge_val = (const float*)d_in[3];
    const float* weight   = (const float*)d_in[4];

    float* femb = (float*)d_out;                              // [N, 128]
    float* x    = (float*)d_out + (size_t)N_NODES * OUT_FEAT; // [N, 128]

    wt_kernel<<<(IN_FEAT * OUT_FEAT + 255) / 256, 256>>>(weight);
    rowptr_scan<<<(N_EDGES + 255) / 256, 256>>>(edge_row);

    int gemm_blocks = (N_NODES + BM - 1) / BM;   // 391
    gemm_tf32_v2<<<gemm_blocks, 256>>>(feat, femb);

    int spmm_blocks = (N_NODES + 7) / 8;         // 8 warps/block
    spmm_kernel<<<spmm_blocks, 256>>>(edge_col, edge_val, femb, x);
}

// round 5
// speedup vs baseline: 1.0006x; 1.0006x over previous
#include <cuda_runtime.h>
#include <cstdint>

#define N_NODES 100000
#define N_EDGES 3200000
#define IN_FEAT 256
#define OUT_FEAT 128

// Scratch (no dynamic alloc allowed)
__device__ int g_row_ptr[N_NODES + 1];
__device__ uint32_t g_wt[IN_FEAT * OUT_FEAT];   // W tf32(rna), [k][n]

__device__ __forceinline__ uint32_t smem_u32(const void* p) {
    uint32_t a;
    asm("{ .reg .u64 t; cvta.to.shared.u64 t, %1; cvt.u32.u64 %0, t; }" : "=r"(a) : "l"(p));
    return a;
}
__device__ __forceinline__ uint32_t f2tf32(float f) {
    uint32_t r;
    asm("cvt.rna.tf32.f32 %0, %1;" : "=r"(r) : "f"(f));
    return r;
}
// cp.async 16B with src-size (0 => zero-fill, src not dereferenced)
__device__ __forceinline__ void cp16z(uint32_t dst, const void* src, int srcsize) {
    asm volatile("cp.async.cg.shared.global [%0], [%1], 16, %2;"
                 :: "r"(dst), "l"(src), "r"(srcsize));
}
__device__ __forceinline__ void cp16(uint32_t dst, const void* src) {
    asm volatile("cp.async.cg.shared.global [%0], [%1], 16;" :: "r"(dst), "l"(src));
}
#define CP_COMMIT() asm volatile("cp.async.commit_group;" ::: "memory")
#define CP_WAIT1()  asm volatile("cp.async.wait_group 1;" ::: "memory")

// ---------------------------------------------------------------------------
__global__ void wt_kernel(const float* __restrict__ W) {
    int t = blockIdx.x * blockDim.x + threadIdx.x;
    if (t < IN_FEAT * OUT_FEAT) g_wt[t] = f2tf32(__ldg(W + t));
}

__global__ void rowptr_scan(const int* __restrict__ edge_row) {
    int e = blockIdx.x * blockDim.x + threadIdx.x;
    if (e >= N_EDGES) return;
    int cur  = __ldg(edge_row + e);
    int prev = (e == 0) ? -1 : __ldg(edge_row + e - 1);
    for (int i = prev + 1; i <= cur; i++) g_row_ptr[i] = e;
    if (e == N_EDGES - 1)
        for (int i = cur + 1; i <= N_NODES; i++) g_row_ptr[i] = N_EDGES;
}

// ---------------------------------------------------------------------------
// GEMM v3: femb = feat @ W, tf32 mma.sync m16n8k8.
// CTA 128x128, BK=16, 3-stage cp.async pipeline (A raw-fp32->tf32 truncation,
// B pre-rounded in g_wt). 8 warps 4(M)x2(N), warp tile 32x64.
// As pitch 20 u32, Bs pitch 136 u32 (conflict-free fragment LDS; 16B-aligned
// rows so cp.async 16B chunks land correctly).
// ---------------------------------------------------------------------------
#define BK 16
#define NCH (IN_FEAT / BK)       // 16
#define STAGES 3
#define AP 20
#define BP 136
#define AS_U32 (128 * AP)        // 2560 u32 = 10240 B per stage
#define BS_U32 (BK * BP)         // 2176 u32 = 8704 B per stage
#define STG_U32 (AS_U32 + BS_U32)
#define SM_TOTAL (STAGES * STG_U32 * 4)   // 56832 B

__global__ void __launch_bounds__(256, 2) gemm_tf32_v3(
    const float* __restrict__ A,   // [M, 256] fp32
    float* __restrict__ C)         // [M, 128] fp32
{
    extern __shared__ uint32_t sm[];
    const uint32_t sb = smem_u32(sm);

    const int tid  = threadIdx.x;
    const int lane = tid & 31;
    const int wid  = tid >> 5;
    const int wm   = wid & 3;          // rows [wm*32, +32)
    const int wn   = wid >> 2;         // cols [wn*64, +64)
    const int row0 = blockIdx.x * 128;
    const int g    = lane >> 2;
    const int q    = lane & 3;

    float acc[2][8][4];
#pragma unroll
    for (int mi = 0; mi < 2; mi++)
#pragma unroll
        for (int ni = 0; ni < 8; ni++)
#pragma unroll
            for (int j = 0; j < 4; j++) acc[mi][ni][j] = 0.0f;

    // A copy: 512 16B-chunks (128 rows x 4), 2 per thread
    const int ar0 = tid >> 2,          ac0 = (tid & 3) * 4;
    const int ar1 = (tid + 256) >> 2,  ac1 = ((tid + 256) & 3) * 4;
    const int asz0 = (row0 + ar0 < N_NODES) ? 16 : 0;
    const int asz1 = (row0 + ar1 < N_NODES) ? 16 : 0;
    const float* asrc0 = A + (size_t)min(row0 + ar0, N_NODES - 1) * IN_FEAT + ac0;
    const float* asrc1 = A + (size_t)min(row0 + ar1, N_NODES - 1) * IN_FEAT + ac1;
    // B copy: 512 16B-chunks (16 k x 32), 2 per thread
    const int bk0 = tid >> 5,          bn0 = (tid & 31) * 4;
    const int bk1 = (tid + 256) >> 5,  bn1 = bn0;

#define ISSUE(c) do {                                                          \
    const int _st = (c) % STAGES;                                              \
    const int _k0 = (c) * BK;                                                  \
    uint32_t _ab = sb + (_st * STG_U32) * 4;                                   \
    uint32_t _bb = _ab + AS_U32 * 4;                                           \
    cp16z(_ab + (ar0 * AP + ac0) * 4, asrc0 + _k0, asz0);                      \
    cp16z(_ab + (ar1 * AP + ac1) * 4, asrc1 + _k0, asz1);                      \
    cp16(_bb + (bk0 * BP + bn0) * 4, g_wt + (_k0 + bk0) * OUT_FEAT + bn0);     \
    cp16(_bb + (bk1 * BP + bn1) * 4, g_wt + (_k0 + bk1) * OUT_FEAT + bn1);     \
    CP_COMMIT();                                                               \
} while (0)

    ISSUE(0);
    ISSUE(1);
    CP_WAIT1();            // stage 0 landed
    __syncthreads();

    for (int c = 0; c < NCH; c++) {
        if (c + 2 < NCH) ISSUE(c + 2);   // overwrites stage (c-1): safe after prev sync

        const uint32_t* As = sm + (c % STAGES) * STG_U32;
        const uint32_t* Bs = As + AS_U32;

#pragma unroll
        for (int ks = 0; ks < BK; ks += 8) {
            uint32_t af[2][4];
#pragma unroll
            for (int mi = 0; mi < 2; mi++) {
                int m = wm * 32 + mi * 16 + g;
                af[mi][0] = As[m * AP + ks + q];
                af[mi][1] = As[(m + 8) * AP + ks + q];
                af[mi][2] = As[m * AP + ks + q + 4];
                af[mi][3] = As[(m + 8) * AP + ks + q + 4];
            }
            uint32_t bf[8][2];
#pragma unroll
            for (int ni = 0; ni < 8; ni++) {
                int n = wn * 64 + ni * 8 + g;
                bf[ni][0] = Bs[(ks + q) * BP + n];
                bf[ni][1] = Bs[(ks + q + 4) * BP + n];
            }
#pragma unroll
            for (int mi = 0; mi < 2; mi++)
#pragma unroll
                for (int ni = 0; ni < 8; ni++) {
                    asm volatile(
                        "mma.sync.aligned.m16n8k8.row.col.f32.tf32.tf32.f32 "
                        "{%0,%1,%2,%3}, {%4,%5,%6,%7}, {%8,%9}, {%0,%1,%2,%3};"
                        : "+f"(acc[mi][ni][0]), "+f"(acc[mi][ni][1]),
                          "+f"(acc[mi][ni][2]), "+f"(acc[mi][ni][3])
                        : "r"(af[mi][0]), "r"(af[mi][1]), "r"(af[mi][2]), "r"(af[mi][3]),
                          "r"(bf[ni][0]), "r"(bf[ni][1]));
                }
        }

        if (c + 1 < NCH) {
            CP_WAIT1();        // stage c+1 landed
            __syncthreads();   // + all warps done with stage c
        }
    }

    // Epilogue: warp tile 32x64
#pragma unroll
    for (int mi = 0; mi < 2; mi++) {
        int r1 = row0 + wm * 32 + mi * 16 + g;
        int r2 = r1 + 8;
#pragma unroll
        for (int ni = 0; ni < 8; ni++) {
            int col = wn * 64 + ni * 8 + 2 * q;
            if (r1 < N_NODES)
                *(float2*)(C + (size_t)r1 * OUT_FEAT + col) =
                    make_float2(acc[mi][ni][0], acc[mi][ni][1]);
            if (r2 < N_NODES)
                *(float2*)(C + (size_t)r2 * OUT_FEAT + col) =
                    make_float2(acc[mi][ni][2], acc[mi][ni][3]);
        }
    }
}

// ---------------------------------------------------------------------------
// SpMM: one warp per node; lane owns 4 cols. 8-way unroll for MLP.
// Edge arrays streamed (__ldcs), x stored evict-first (__stcs).
// ---------------------------------------------------------------------------
__global__ __launch_bounds__(256) void spmm_kernel(
    const int* __restrict__ edge_col,
    const float* __restrict__ edge_val,
    const float* __restrict__ femb,
    float* __restrict__ x)
{
    int warp = (blockIdx.x * blockDim.x + threadIdx.x) >> 5;
    if (warp >= N_NODES) return;
    int lane = threadIdx.x & 31;

    int s = g_row_ptr[warp];
    int e = g_row_ptr[warp + 1];

    float4 acc = make_float4(0.f, 0.f, 0.f, 0.f);
    int i = s;

    for (; i + 8 <= e; i += 8) {
        int   c[8];
        float v[8];
#pragma unroll
        for (int j = 0; j < 8; j++) c[j] = __ldcs(edge_col + i + j);
#pragma unroll
        for (int j = 0; j < 8; j++) v[j] = __ldcs(edge_val + i + j);
        float4 f[8];
#pragma unroll
        for (int j = 0; j < 8; j++)
            f[j] = *(const float4*)(femb + (size_t)c[j] * OUT_FEAT + lane * 4);
#pragma unroll
        for (int j = 0; j < 8; j++) {
            acc.x = fmaf(v[j], f[j].x, acc.x);
            acc.y = fmaf(v[j], f[j].y, acc.y);
            acc.z = fmaf(v[j], f[j].z, acc.z);
            acc.w = fmaf(v[j], f[j].w, acc.w);
        }
    }
    for (; i < e; i++) {
        int   c = __ldcs(edge_col + i);
        float v = __ldcs(edge_val + i);
        float4 f = *(const float4*)(femb + (size_t)c * OUT_FEAT + lane * 4);
        acc.x = fmaf(v, f.x, acc.x);
        acc.y = fmaf(v, f.y, acc.y);
        acc.z = fmaf(v, f.z, acc.z);
        acc.w = fmaf(v, f.w, acc.w);
    }
    __stcs((float4*)(x + (size_t)warp * OUT_FEAT + lane * 4), acc);
}

// ---------------------------------------------------------------------------
extern "C" void kernel_launch(void* const* d_in, const int* in_sizes, int n_in,
                              void* d_out, int out_size)
{
    const float* feat     = (const float*)d_in[0];
    const int*   edge_row = (const int*)d_in[1];
    const int*   edge_col = (const int*)d_in[2];
    const float* edge_val = (const float*)d_in[3];
    const float* weight   = (const float*)d_in[4];

    float* femb = (float*)d_out;                              // [N, 128]
    float* x    = (float*)d_out + (size_t)N_NODES * OUT_FEAT; // [N, 128]

    static bool attr_set = false;
    if (!attr_set) {
        cudaFuncSetAttribute(gemm_tf32_v3, cudaFuncAttributeMaxDynamicSharedMemorySize, SM_TOTAL);
        attr_set = true;
    }

    wt_kernel<<<(IN_FEAT * OUT_FEAT + 255) / 256, 256>>>(weight);
    rowptr_scan<<<(N_EDGES + 255) / 256, 256>>>(edge_row);

    int gemm_blocks = (N_NODES + 127) / 128;   // 782
    gemm_tf32_v3<<<gemm_blocks, 256, SM_TOTAL>>>(feat, femb);

    int spmm_blocks = (N_NODES + 7) / 8;
    spmm_kernel<<<spmm_blocks, 256>>>(edge_col, edge_val, femb, x);
}

// round 7
// speedup vs baseline: 1.1552x; 1.1545x over previous
#include <cuda_runtime.h>
#include <cuda_fp16.h>
#include <cstdint>

#define N_NODES 100000
#define N_EDGES 3200000
#define IN_FEAT 256
#define OUT_FEAT 128

// Scratch (no dynamic alloc allowed)
__device__ int g_row_ptr[N_NODES + 1];
__device__ uint32_t g_wt[IN_FEAT * OUT_FEAT];          // W tf32(rna), [k][n]
__device__ __half g_femb16[(size_t)N_NODES * OUT_FEAT]; // fp16 shadow of femb

__device__ __forceinline__ uint32_t smem_u32(const void* p) {
    uint32_t a;
    asm("{ .reg .u64 t; cvta.to.shared.u64 t, %1; cvt.u32.u64 %0, t; }" : "=r"(a) : "l"(p));
    return a;
}
__device__ __forceinline__ uint32_t f2tf32(float f) {
    uint32_t r;
    asm("cvt.rna.tf32.f32 %0, %1;" : "=r"(r) : "f"(f));
    return r;
}
// cp.async 16B with src-size (0 => zero-fill, src not dereferenced)
__device__ __forceinline__ void cp16z(uint32_t dst, const void* src, int srcsize) {
    asm volatile("cp.async.cg.shared.global [%0], [%1], 16, %2;"
                 :: "r"(dst), "l"(src), "r"(srcsize));
}
__device__ __forceinline__ void cp16(uint32_t dst, const void* src) {
    asm volatile("cp.async.cg.shared.global [%0], [%1], 16;" :: "r"(dst), "l"(src));
}
#define CP_COMMIT() asm volatile("cp.async.commit_group;" ::: "memory")
#define CP_WAIT1()  asm volatile("cp.async.wait_group 1;" ::: "memory")

// ---------------------------------------------------------------------------
__global__ void wt_kernel(const float* __restrict__ W) {
    int t = blockIdx.x * blockDim.x + threadIdx.x;
    if (t < IN_FEAT * OUT_FEAT) g_wt[t] = f2tf32(__ldg(W + t));
}

__global__ void rowptr_scan(const int* __restrict__ edge_row) {
    int e = blockIdx.x * blockDim.x + threadIdx.x;
    if (e >= N_EDGES) return;
    int cur  = __ldg(edge_row + e);
    int prev = (e == 0) ? -1 : __ldg(edge_row + e - 1);
    for (int i = prev + 1; i <= cur; i++) g_row_ptr[i] = e;
    if (e == N_EDGES - 1)
        for (int i = cur + 1; i <= N_NODES; i++) g_row_ptr[i] = N_EDGES;
}

// ---------------------------------------------------------------------------
// GEMM v3 (measured-good in R5): femb = feat @ W, tf32 mma.sync m16n8k8.
// CTA 128x128, BK=16, 3-stage cp.async pipeline (A raw-fp32->tf32 truncation,
// B pre-rounded in g_wt). 8 warps 4(M)x2(N), warp tile 32x64.
// Epilogue additionally writes fp16 shadow copy for the SpMM gather.
// ---------------------------------------------------------------------------
#define BK 16
#define NCH (IN_FEAT / BK)       // 16
#define STAGES 3
#define AP 20
#define BP 136
#define AS_U32 (128 * AP)        // 2560 u32 = 10240 B per stage
#define BS_U32 (BK * BP)         // 2176 u32 = 8704 B per stage
#define STG_U32 (AS_U32 + BS_U32)
#define SM_TOTAL (STAGES * STG_U32 * 4)   // 56832 B

__global__ void __launch_bounds__(256, 2) gemm_tf32_v3(
    const float* __restrict__ A,   // [M, 256] fp32
    float* __restrict__ C)         // [M, 128] fp32
{
    extern __shared__ uint32_t sm[];
    const uint32_t sb = smem_u32(sm);

    const int tid  = threadIdx.x;
    const int lane = tid & 31;
    const int wid  = tid >> 5;
    const int wm   = wid & 3;          // rows [wm*32, +32)
    const int wn   = wid >> 2;         // cols [wn*64, +64)
    const int row0 = blockIdx.x * 128;
    const int g    = lane >> 2;
    const int q    = lane & 3;

    float acc[2][8][4];
#pragma unroll
    for (int mi = 0; mi < 2; mi++)
#pragma unroll
        for (int ni = 0; ni < 8; ni++)
#pragma unroll
            for (int j = 0; j < 4; j++) acc[mi][ni][j] = 0.0f;

    // A copy: 512 16B-chunks (128 rows x 4), 2 per thread
    const int ar0 = tid >> 2,          ac0 = (tid & 3) * 4;
    const int ar1 = (tid + 256) >> 2,  ac1 = ((tid + 256) & 3) * 4;
    const int asz0 = (row0 + ar0 < N_NODES) ? 16 : 0;
    const int asz1 = (row0 + ar1 < N_NODES) ? 16 : 0;
    const float* asrc0 = A + (size_t)min(row0 + ar0, N_NODES - 1) * IN_FEAT + ac0;
    const float* asrc1 = A + (size_t)min(row0 + ar1, N_NODES - 1) * IN_FEAT + ac1;
    // B copy: 512 16B-chunks (16 k x 32), 2 per thread
    const int bk0 = tid >> 5,          bn0 = (tid & 31) * 4;
    const int bk1 = (tid + 256) >> 5,  bn1 = bn0;

#define ISSUE(c) do {                                                          \
    const int _st = (c) % STAGES;                                              \
    const int _k0 = (c) * BK;                                                  \
    uint32_t _ab = sb + (_st * STG_U32) * 4;                                   \
    uint32_t _bb = _ab + AS_U32 * 4;                                           \
    cp16z(_ab + (ar0 * AP + ac0) * 4, asrc0 + _k0, asz0);                      \
    cp16z(_ab + (ar1 * AP + ac1) * 4, asrc1 + _k0, asz1);                      \
    cp16(_bb + (bk0 * BP + bn0) * 4, g_wt + (_k0 + bk0) * OUT_FEAT + bn0);     \
    cp16(_bb + (bk1 * BP + bn1) * 4, g_wt + (_k0 + bk1) * OUT_FEAT + bn1);     \
    CP_COMMIT();                                                               \
} while (0)

    ISSUE(0);
    ISSUE(1);
    CP_WAIT1();            // stage 0 landed
    __syncthreads();

    for (int c = 0; c < NCH; c++) {
        if (c + 2 < NCH) ISSUE(c + 2);   // overwrites stage (c-1): safe after prev sync

        const uint32_t* As = sm + (c % STAGES) * STG_U32;
        const uint32_t* Bs = As + AS_U32;

#pragma unroll
        for (int ks = 0; ks < BK; ks += 8) {
            uint32_t af[2][4];
#pragma unroll
            for (int mi = 0; mi < 2; mi++) {
                int m = wm * 32 + mi * 16 + g;
                af[mi][0] = As[m * AP + ks + q];
                af[mi][1] = As[(m + 8) * AP + ks + q];
                af[mi][2] = As[m * AP + ks + q + 4];
                af[mi][3] = As[(m + 8) * AP + ks + q + 4];
            }
            uint32_t bf[8][2];
#pragma unroll
            for (int ni = 0; ni < 8; ni++) {
                int n = wn * 64 + ni * 8 + g;
                bf[ni][0] = Bs[(ks + q) * BP + n];
                bf[ni][1] = Bs[(ks + q + 4) * BP + n];
            }
#pragma unroll
            for (int mi = 0; mi < 2; mi++)
#pragma unroll
                for (int ni = 0; ni < 8; ni++) {
                    asm volatile(
                        "mma.sync.aligned.m16n8k8.row.col.f32.tf32.tf32.f32 "
                        "{%0,%1,%2,%3}, {%4,%5,%6,%7}, {%8,%9}, {%0,%1,%2,%3};"
                        : "+f"(acc[mi][ni][0]), "+f"(acc[mi][ni][1]),
                          "+f"(acc[mi][ni][2]), "+f"(acc[mi][ni][3])
                        : "r"(af[mi][0]), "r"(af[mi][1]), "r"(af[mi][2]), "r"(af[mi][3]),
                          "r"(bf[ni][0]), "r"(bf[ni][1]));
                }
        }

        if (c + 1 < NCH) {
            CP_WAIT1();        // stage c+1 landed
            __syncthreads();   // + all warps done with stage c
        }
    }

    // Epilogue: fp32 to C, fp16 shadow to g_femb16.
#pragma unroll
    for (int mi = 0; mi < 2; mi++) {
        int r1 = row0 + wm * 32 + mi * 16 + g;
        int r2 = r1 + 8;
#pragma unroll
        for (int ni = 0; ni < 8; ni++) {
            int col = wn * 64 + ni * 8 + 2 * q;
            if (r1 < N_NODES) {
                *(float2*)(C + (size_t)r1 * OUT_FEAT + col) =
                    make_float2(acc[mi][ni][0], acc[mi][ni][1]);
                *(__half2*)(g_femb16 + (size_t)r1 * OUT_FEAT + col) =
                    __floats2half2_rn(acc[mi][ni][0], acc[mi][ni][1]);
            }
            if (r2 < N_NODES) {
                *(float2*)(C + (size_t)r2 * OUT_FEAT + col) =
                    make_float2(acc[mi][ni][2], acc[mi][ni][3]);
                *(__half2*)(g_femb16 + (size_t)r2 * OUT_FEAT + col) =
                    __floats2half2_rn(acc[mi][ni][2], acc[mi][ni][3]);
            }
        }
    }
}

// ---------------------------------------------------------------------------
// SpMM: one warp per node; lane owns 4 cols. Gather from fp16 shadow
// (halves L2 traffic vs fp32), accumulate fp32. 4-way unroll (proven best).
// ---------------------------------------------------------------------------
__global__ __launch_bounds__(256) void spmm_kernel(
    const int* __restrict__ edge_col,
    const float* __restrict__ edge_val,
    float* __restrict__ x)
{
    int warp = (blockIdx.x * blockDim.x + threadIdx.x) >> 5;
    if (warp >= N_NODES) return;
    int lane = threadIdx.x & 31;

    int s = g_row_ptr[warp];
    int e = g_row_ptr[warp + 1];

    const __half2* fb = (const __half2*)g_femb16;   // [N * 64] half2

    float4 acc = make_float4(0.f, 0.f, 0.f, 0.f);
    int i = s;
    for (; i + 4 <= e; i += 4) {
        int c0 = __ldg(edge_col + i + 0);
        int c1 = __ldg(edge_col + i + 1);
        int c2 = __ldg(edge_col + i + 2);
        int c3 = __ldg(edge_col + i + 3);
        float v0 = __ldg(edge_val + i + 0);
        float v1 = __ldg(edge_val + i + 1);
        float v2 = __ldg(edge_val + i + 2);
        float v3 = __ldg(edge_val + i + 3);
        // 8B gather per lane: two half2 = 4 columns
        __half2 h0a, h0b, h1a, h1b, h2a, h2b, h3a, h3b;
        { uint2 u = *(const uint2*)(fb + (size_t)c0 * 64 + lane * 2);
          h0a = *(__half2*)&u.x; h0b = *(__half2*)&u.y; }
        { uint2 u = *(const uint2*)(fb + (size_t)c1 * 64 + lane * 2);
          h1a = *(__half2*)&u.x; h1b = *(__half2*)&u.y; }
        { uint2 u = *(const uint2*)(fb + (size_t)c2 * 64 + lane * 2);
          h2a = *(__half2*)&u.x; h2b = *(__half2*)&u.y; }
        { uint2 u = *(const uint2*)(fb + (size_t)c3 * 64 + lane * 2);
          h3a = *(__half2*)&u.x; h3b = *(__half2*)&u.y; }
        float2 f;
        f = __half22float2(h0a); acc.x = fmaf(v0, f.x, acc.x); acc.y = fmaf(v0, f.y, acc.y);
        f = __half22float2(h0b); acc.z = fmaf(v0, f.x, acc.z); acc.w = fmaf(v0, f.y, acc.w);
        f = __half22float2(h1a); acc.x = fmaf(v1, f.x, acc.x); acc.y = fmaf(v1, f.y, acc.y);
        f = __half22float2(h1b); acc.z = fmaf(v1, f.x, acc.z); acc.w = fmaf(v1, f.y, acc.w);
        f = __half22float2(h2a); acc.x = fmaf(v2, f.x, acc.x); acc.y = fmaf(v2, f.y, acc.y);
        f = __half22float2(h2b); acc.z = fmaf(v2, f.x, acc.z); acc.w = fmaf(v2, f.y, acc.w);
        f = __half22float2(h3a); acc.x = fmaf(v3, f.x, acc.x); acc.y = fmaf(v3, f.y, acc.y);
        f = __half22float2(h3b); acc.z = fmaf(v3, f.x, acc.z); acc.w = fmaf(v3, f.y, acc.w);
    }
    for (; i < e; i++) {
        int c = __ldg(edge_col + i);
        float v = __ldg(edge_val + i);
        uint2 u = *(const uint2*)(fb + (size_t)c * 64 + lane * 2);
        float2 fa = __half22float2(*(__half2*)&u.x);
        float2 fbv = __half22float2(*(__half2*)&u.y);
        acc.x = fmaf(v, fa.x, acc.x); acc.y = fmaf(v, fa.y, acc.y);
        acc.z = fmaf(v, fbv.x, acc.z); acc.w = fmaf(v, fbv.y, acc.w);
    }
    *(float4*)(x + (size_t)warp * OUT_FEAT + lane * 4) = acc;
}

// ---------------------------------------------------------------------------
extern "C" void kernel_launch(void* const* d_in, const int* in_sizes, int n_in,
                              void* d_out, int out_size)
{
    const float* feat     = (const float*)d_in[0];
    const int*   edge_row = (const int*)d_in[1];
    const int*   edge_col = (const int*)d_in[2];
    const float* edge_val = (const float*)d_in[3];
    const float* weight   = (const float*)d_in[4];

    float* femb = (float*)d_out;                              // [N, 128]
    float* x    = (float*)d_out + (size_t)N_NODES * OUT_FEAT; // [N, 128]

    cudaFuncSetAttribute(gemm_tf32_v3, cudaFuncAttributeMaxDynamicSharedMemorySize, SM_TOTAL);

    wt_kernel<<<(IN_FEAT * OUT_FEAT + 255) / 256, 256>>>(weight);
    rowptr_scan<<<(N_EDGES + 255) / 256, 256>>>(edge_row);

    int gemm_blocks = (N_NODES + 127) / 128;   // 782
    gemm_tf32_v3<<<gemm_blocks, 256, SM_TOTAL>>>(feat, femb);

    int spmm_blocks = (N_NODES + 7) / 8;
    spmm_kernel<<<spmm_blocks, 256>>>(edge_col, edge_val, x);
}